// round 15
// baseline (speedup 1.0000x reference)
#include <cuda_runtime.h>
#include <cuda_fp16.h>
#include <cuda_bf16.h>

// fp16 cache of L2-normalized embedding rows. N = 100000, H = 128.
// Single 33.5 MB table; emb(51.2) + table(33.5) < L2 (126 MB) -> resident.
#define MAX_N 131072
__device__ uint2 g_en16[MAX_N * 32];   // row*32 + lane -> 4 halves (8 B)

// Kernel A: each warp normalizes TWO rows (independent loads -> MLP=2,
// interleaved shuffle reductions), writes fp16 rows.
__global__ void norm16_kernel(const float* __restrict__ emb, int N) {
    int pair = blockIdx.x * (blockDim.x >> 5) + (threadIdx.x >> 5);
    int lane = threadIdx.x & 31;
    int r0 = pair * 2;
    int r1 = r0 + 1;
    if (r0 >= N) return;
    bool has1 = (r1 < N);

    const float4* p0 = reinterpret_cast<const float4*>(emb) + (size_t)r0 * 32;
    const float4* p1 = reinterpret_cast<const float4*>(emb) + (size_t)(has1 ? r1 : r0) * 32;
    float4 v0 = __ldg(&p0[lane]);
    float4 v1 = __ldg(&p1[lane]);

    float s0 = v0.x * v0.x + v0.y * v0.y + v0.z * v0.z + v0.w * v0.w;
    float s1 = v1.x * v1.x + v1.y * v1.y + v1.z * v1.z + v1.w * v1.w;
    #pragma unroll
    for (int o = 16; o > 0; o >>= 1) {
        s0 += __shfl_xor_sync(0xffffffffu, s0, o);
        s1 += __shfl_xor_sync(0xffffffffu, s1, o);
    }
    float i0 = 1.0f / fmaxf(sqrtf(s0), 1e-12f);
    float i1 = 1.0f / fmaxf(sqrtf(s1), 1e-12f);

    __half2 a0 = __float22half2_rn(make_float2(v0.x * i0, v0.y * i0));
    __half2 a1 = __float22half2_rn(make_float2(v0.z * i0, v0.w * i0));
    uint2 pe0;
    pe0.x = *reinterpret_cast<unsigned int*>(&a0);
    pe0.y = *reinterpret_cast<unsigned int*>(&a1);
    g_en16[(size_t)r0 * 32 + lane] = pe0;

    if (has1) {
        __half2 b0 = __float22half2_rn(make_float2(v1.x * i1, v1.y * i1));
        __half2 b1 = __float22half2_rn(make_float2(v1.z * i1, v1.w * i1));
        uint2 pe1;
        pe1.x = *reinterpret_cast<unsigned int*>(&b0);
        pe1.y = *reinterpret_cast<unsigned int*>(&b1);
        g_en16[(size_t)r1 * 32 + lane] = pe1;
    }
}

// Packed-half dot: (a .* d) . b over 8 halves, half2 accumulate.
__device__ __forceinline__ __half2 dot8h(uint4 a, uint4 b,
                                         const __half2* __restrict__ dh,
                                         __half2 acc) {
    const __half2* pa = reinterpret_cast<const __half2*>(&a);
    const __half2* pb = reinterpret_cast<const __half2*>(&b);
    #pragma unroll
    for (int k = 0; k < 4; k++)
        acc = __hfma2(__hmul2(pa[k], dh[k]), pb[k], acc);
    return acc;
}

// L2-only 16-byte gather (.cg): table lines have ~0 L1 hit probability, so
// skipping L1 allocation removes useless fill/evict work from L1tex.
__device__ __forceinline__ uint4 ldcg16(const uint4* p) {
    return __ldcg(p);
}

// Kernel B: persistent warps, 8 edges per warp per iteration, 8 lanes/edge,
// 8 independent full-line LDG.128.CG gathers per lane, packed-half dot.
// At the chip LTS throughput cap (~12 TB/s for 320 MB -> ~26.5 us).
__global__ void __launch_bounds__(256, 7) edge_kernel(
        const int* __restrict__ src,
        const int* __restrict__ dst,
        const float* __restrict__ dvec,
        const float* __restrict__ scale,
        float* __restrict__ out,
        int E) {
    int lane = threadIdx.x & 31;
    int g    = lane >> 3;                // edge group: 0..3
    int l8   = lane & 7;                 // lane within group

    int warp_global = blockIdx.x * (blockDim.x >> 5) + (threadIdx.x >> 5);
    int nwarps      = gridDim.x * (blockDim.x >> 5);
    int stride      = nwarps * 8;

    float sc = __ldg(scale);
    const uint4* en = reinterpret_cast<const uint4*>(g_en16);

    __half2 d0[4], d1[4];
    {
        const float2* dp = reinterpret_cast<const float2*>(dvec);
        #pragma unroll
        for (int k = 0; k < 4; k++) {
            d0[k] = __float22half2_rn(__ldg(&dp[4 * l8 + k]));
            d1[k] = __float22half2_rn(__ldg(&dp[32 + 4 * l8 + k]));
        }
    }

    int base = warp_global * 8;
    if (base >= E) return;

    int eA = base + g, eB = base + 4 + g;
    int sA = __ldg(&src[min(eA, E - 1)]);
    int tA = __ldg(&dst[min(eA, E - 1)]);
    int sB = __ldg(&src[min(eB, E - 1)]);
    int tB = __ldg(&dst[min(eB, E - 1)]);

    for (; base < E; base += stride) {
        eA = base + g;
        eB = base + 4 + g;

        int nb = base + stride;
        int sAn = 0, tAn = 0, sBn = 0, tBn = 0;
        if (nb < E) {
            int neA = min(nb + g, E - 1);
            int neB = min(nb + 4 + g, E - 1);
            sAn = __ldg(&src[neA]);
            tAn = __ldg(&dst[neA]);
            sBn = __ldg(&src[neB]);
            tBn = __ldg(&dst[neB]);
        }

        const uint4* rsA = en + (size_t)sA * 16;
        const uint4* rtA = en + (size_t)tA * 16;
        const uint4* rsB = en + (size_t)sB * 16;
        const uint4* rtB = en + (size_t)tB * 16;

        uint4 a0 = ldcg16(&rsA[l8]);
        uint4 a1 = ldcg16(&rsA[l8 + 8]);
        uint4 b0 = ldcg16(&rtA[l8]);
        uint4 b1 = ldcg16(&rtA[l8 + 8]);
        uint4 c0 = ldcg16(&rsB[l8]);
        uint4 c1 = ldcg16(&rsB[l8 + 8]);
        uint4 f0 = ldcg16(&rtB[l8]);
        uint4 f1 = ldcg16(&rtB[l8 + 8]);

        __half2 z = __float2half2_rn(0.0f);
        __half2 aAcc = dot8h(a1, b1, d1, dot8h(a0, b0, d0, z));
        __half2 bAcc = dot8h(c1, f1, d1, dot8h(c0, f0, d0, z));

        float2 fA = __half22float2(aAcc);
        float2 fB = __half22float2(bAcc);
        float pA = fA.x + fA.y;
        float pB = fB.x + fB.y;

        #pragma unroll
        for (int o = 4; o > 0; o >>= 1) {
            pA += __shfl_xor_sync(0xffffffffu, pA, o);
            pB += __shfl_xor_sync(0xffffffffu, pB, o);
        }

        if (l8 == 0) {
            if (eA < E) __stcs(&out[eA], pA * sc);
            if (eB < E) __stcs(&out[eB], pB * sc);
        }

        sA = sAn; tA = tAn; sB = sBn; tB = tBn;
    }
}

extern "C" void kernel_launch(void* const* d_in, const int* in_sizes, int n_in,
                              void* d_out, int out_size) {
    const float* emb   = (const float*)d_in[0];
    const int*   src   = (const int*)d_in[1];
    const int*   dst   = (const int*)d_in[2];
    const float* dvec  = (const float*)d_in[3];
    const float* scale = (const float*)d_in[4];
    float* out = (float*)d_out;

    int N = in_sizes[0] / 128;   // H = 128
    int E = in_sizes[1];

    const int TPB = 256;
    int warps_per_block = TPB / 32;

    // A: normalize, 2 rows per warp.
    int pairs = (N + 1) / 2;
    int norm_blocks = (pairs + warps_per_block - 1) / warps_per_block;
    norm16_kernel<<<norm_blocks, TPB>>>(emb, N);

    // B: one exact wave: 7 blocks/SM * 148 SMs.
    int edge_blocks = 148 * 7;
    int max_blocks = (E + warps_per_block * 8 - 1) / (warps_per_block * 8);
    if (edge_blocks > max_blocks) edge_blocks = max_blocks;
    edge_kernel<<<edge_blocks, TPB>>>(src, dst, dvec, scale, out, E);
}

// round 16
// speedup vs baseline: 1.3080x; 1.3080x over previous
#include <cuda_runtime.h>
#include <cuda_fp16.h>
#include <cuda_bf16.h>

// fp16 cache of L2-normalized embedding rows. N = 100000, H = 128.
// Single 33.5 MB table; emb(51.2) + table(33.5) < L2 (126 MB) -> resident.
// Chip-wide L1 (148 x 228 KB ~ 33.7 MB) ~ table size: default-cached gathers
// get a real L1 hit fraction (R15 proved .cg loses it -> +6 us regression).
#define MAX_N 131072
__device__ uint2 g_en16[MAX_N * 32];   // row*32 + lane -> 4 halves (8 B)

// Kernel A: each warp normalizes TWO rows (independent loads -> MLP=2,
// interleaved shuffle reductions), writes fp16 rows.
__global__ void norm16_kernel(const float* __restrict__ emb, int N) {
    int pair = blockIdx.x * (blockDim.x >> 5) + (threadIdx.x >> 5);
    int lane = threadIdx.x & 31;
    int r0 = pair * 2;
    int r1 = r0 + 1;
    if (r0 >= N) return;
    bool has1 = (r1 < N);

    const float4* p0 = reinterpret_cast<const float4*>(emb) + (size_t)r0 * 32;
    const float4* p1 = reinterpret_cast<const float4*>(emb) + (size_t)(has1 ? r1 : r0) * 32;
    float4 v0 = __ldg(&p0[lane]);
    float4 v1 = __ldg(&p1[lane]);

    float s0 = v0.x * v0.x + v0.y * v0.y + v0.z * v0.z + v0.w * v0.w;
    float s1 = v1.x * v1.x + v1.y * v1.y + v1.z * v1.z + v1.w * v1.w;
    #pragma unroll
    for (int o = 16; o > 0; o >>= 1) {
        s0 += __shfl_xor_sync(0xffffffffu, s0, o);
        s1 += __shfl_xor_sync(0xffffffffu, s1, o);
    }
    float i0 = 1.0f / fmaxf(sqrtf(s0), 1e-12f);
    float i1 = 1.0f / fmaxf(sqrtf(s1), 1e-12f);

    __half2 a0 = __float22half2_rn(make_float2(v0.x * i0, v0.y * i0));
    __half2 a1 = __float22half2_rn(make_float2(v0.z * i0, v0.w * i0));
    uint2 pe0;
    pe0.x = *reinterpret_cast<unsigned int*>(&a0);
    pe0.y = *reinterpret_cast<unsigned int*>(&a1);
    g_en16[(size_t)r0 * 32 + lane] = pe0;

    if (has1) {
        __half2 b0 = __float22half2_rn(make_float2(v1.x * i1, v1.y * i1));
        __half2 b1 = __float22half2_rn(make_float2(v1.z * i1, v1.w * i1));
        uint2 pe1;
        pe1.x = *reinterpret_cast<unsigned int*>(&b0);
        pe1.y = *reinterpret_cast<unsigned int*>(&b1);
        g_en16[(size_t)r1 * 32 + lane] = pe1;
    }
}

// Packed-half dot: (a .* d) . b over 8 halves, half2 accumulate.
__device__ __forceinline__ __half2 dot8h(uint4 a, uint4 b,
                                         const __half2* __restrict__ dh,
                                         __half2 acc) {
    const __half2* pa = reinterpret_cast<const __half2*>(&a);
    const __half2* pb = reinterpret_cast<const __half2*>(&b);
    #pragma unroll
    for (int k = 0; k < 4; k++)
        acc = __hfma2(__hmul2(pa[k], dh[k]), pb[k], acc);
    return acc;
}

// Kernel B (proven best: 26.4-27.1 us across rounds): persistent warps,
// 8 edges per warp per iteration, 8 lanes/edge, 8 independent full-line
// LDG.128 (default caching) gathers per lane, packed-half dot, index
// prefetch pipeline, streaming output stores.
__global__ void __launch_bounds__(256, 6) edge_kernel(
        const int* __restrict__ src,
        const int* __restrict__ dst,
        const float* __restrict__ dvec,
        const float* __restrict__ scale,
        float* __restrict__ out,
        int E) {
    int lane = threadIdx.x & 31;
    int g    = lane >> 3;                // edge group: 0..3
    int l8   = lane & 7;                 // lane within group

    int warp_global = blockIdx.x * (blockDim.x >> 5) + (threadIdx.x >> 5);
    int nwarps      = gridDim.x * (blockDim.x >> 5);
    int stride      = nwarps * 8;

    float sc = __ldg(scale);
    const uint4* en = reinterpret_cast<const uint4*>(g_en16);

    __half2 d0[4], d1[4];
    {
        const float2* dp = reinterpret_cast<const float2*>(dvec);
        #pragma unroll
        for (int k = 0; k < 4; k++) {
            d0[k] = __float22half2_rn(__ldg(&dp[4 * l8 + k]));
            d1[k] = __float22half2_rn(__ldg(&dp[32 + 4 * l8 + k]));
        }
    }

    int base = warp_global * 8;
    if (base >= E) return;

    int eA = base + g, eB = base + 4 + g;
    int sA = __ldg(&src[min(eA, E - 1)]);
    int tA = __ldg(&dst[min(eA, E - 1)]);
    int sB = __ldg(&src[min(eB, E - 1)]);
    int tB = __ldg(&dst[min(eB, E - 1)]);

    for (; base < E; base += stride) {
        eA = base + g;
        eB = base + 4 + g;

        int nb = base + stride;
        int sAn = 0, tAn = 0, sBn = 0, tBn = 0;
        if (nb < E) {
            int neA = min(nb + g, E - 1);
            int neB = min(nb + 4 + g, E - 1);
            sAn = __ldg(&src[neA]);
            tAn = __ldg(&dst[neA]);
            sBn = __ldg(&src[neB]);
            tBn = __ldg(&dst[neB]);
        }

        const uint4* rsA = en + (size_t)sA * 16;
        const uint4* rtA = en + (size_t)tA * 16;
        const uint4* rsB = en + (size_t)sB * 16;
        const uint4* rtB = en + (size_t)tB * 16;

        uint4 a0 = __ldg(&rsA[l8]);
        uint4 a1 = __ldg(&rsA[l8 + 8]);
        uint4 b0 = __ldg(&rtA[l8]);
        uint4 b1 = __ldg(&rtA[l8 + 8]);
        uint4 c0 = __ldg(&rsB[l8]);
        uint4 c1 = __ldg(&rsB[l8 + 8]);
        uint4 f0 = __ldg(&rtB[l8]);
        uint4 f1 = __ldg(&rtB[l8 + 8]);

        __half2 z = __float2half2_rn(0.0f);
        __half2 aAcc = dot8h(a1, b1, d1, dot8h(a0, b0, d0, z));
        __half2 bAcc = dot8h(c1, f1, d1, dot8h(c0, f0, d0, z));

        float2 fA = __half22float2(aAcc);
        float2 fB = __half22float2(bAcc);
        float pA = fA.x + fA.y;
        float pB = fB.x + fB.y;

        #pragma unroll
        for (int o = 4; o > 0; o >>= 1) {
            pA += __shfl_xor_sync(0xffffffffu, pA, o);
            pB += __shfl_xor_sync(0xffffffffu, pB, o);
        }

        if (l8 == 0) {
            if (eA < E) __stcs(&out[eA], pA * sc);
            if (eB < E) __stcs(&out[eB], pB * sc);
        }

        sA = sAn; tA = tAn; sB = sBn; tB = tBn;
    }
}

extern "C" void kernel_launch(void* const* d_in, const int* in_sizes, int n_in,
                              void* d_out, int out_size) {
    const float* emb   = (const float*)d_in[0];
    const int*   src   = (const int*)d_in[1];
    const int*   dst   = (const int*)d_in[2];
    const float* dvec  = (const float*)d_in[3];
    const float* scale = (const float*)d_in[4];
    float* out = (float*)d_out;

    int N = in_sizes[0] / 128;   // H = 128
    int E = in_sizes[1];

    const int TPB = 256;
    int warps_per_block = TPB / 32;

    // A: normalize, 2 rows per warp.
    int pairs = (N + 1) / 2;
    int norm_blocks = (pairs + warps_per_block - 1) / warps_per_block;
    norm16_kernel<<<norm_blocks, TPB>>>(emb, N);

    // B: one exact wave: 6 blocks/SM * 148 SMs.
    int edge_blocks = 148 * 6;
    int max_blocks = (E + warps_per_block * 8 - 1) / (warps_per_block * 8);
    if (edge_blocks > max_blocks) edge_blocks = max_blocks;
    edge_kernel<<<edge_blocks, TPB>>>(src, dst, dvec, scale, out, E);
}